// round 9
// baseline (speedup 1.0000x reference)
#include <cuda_runtime.h>
#include <math.h>

#define C       3
#define T       32
#define H       512
#define W       512
#define PS      32
#define NH      (H / PS)
#define NW      (W / PS)
#define NPATCH  (T * NH * NW)     // 8192
#define PATCH_ELEMS (C * PS * PS) // 3072
#define PPB     8                 // patches per CTA
#define GRID    (NPATCH / PPB)    // 1024

__device__ int          g_frame_max[T];   // zero-initialized
__device__ unsigned int g_count;          // zero-initialized

__global__ __launch_bounds__(256)
void patch_loss_kernel(const float* __restrict__ x,
                       const float* __restrict__ xr,
                       float* __restrict__ out) {
    const int base  = blockIdx.x * PPB;
    const int t     = base >> 8;           // frame (shared by the 8 patches)
    const int rem   = base & 255;
    const int ih    = rem >> 4;            // row band (shared)
    const int iw0   = rem & 15;            // first of 8 consecutive iw blocks

    const int tid = threadIdx.x;
    const int r = tid >> 3;                // row within patch [0,32)
    const int q = tid & 7;                 // float4 within row [0,8)

    const int hrow = ih * PS + r;
    const int idx0 = (t * H + hrow) * W + iw0 * PS + q * 4;
    const int cstride = T * H * W;

    float s[PPB];
#pragma unroll
    for (int p = 0; p < PPB; ++p) s[p] = 0.0f;

#pragma unroll
    for (int c = 0; c < C; ++c) {
        const int cidx = idx0 + c * cstride;
#pragma unroll
        for (int p = 0; p < PPB; ++p) {
            const int idx = cidx + p * PS;
            const float4 a = __ldg(reinterpret_cast<const float4*>(x  + idx));
            const float4 b = __ldg(reinterpret_cast<const float4*>(xr + idx));
            s[p] += fabsf(a.x - b.x) + fabsf(a.y - b.y)
                  + fabsf(a.z - b.z) + fabsf(a.w - b.w);
        }
    }

    // Per-warp reduce of the 8 patch partials.
    __shared__ float warp_sums[PPB][8];    // [patch][warp] = 64 floats
    const int lane = tid & 31;
    const int wid  = tid >> 5;
#pragma unroll
    for (int p = 0; p < PPB; ++p) {
        float v = s[p];
#pragma unroll
        for (int off = 16; off > 0; off >>= 1)
            v += __shfl_down_sync(0xFFFFFFFFu, v, off);
        if (lane == 0) warp_sums[p][wid] = v;
    }
    __syncthreads();

    if (wid == 0) {
        // 64 partials, 32 lanes: lane -> patch = lane>>2, folds warps
        // (lane&3) and (lane&3)+4; then 4-lane tree per patch.
        const int p  = lane >> 2;
        const int w0 = lane & 3;
        float v = warp_sums[p][w0] + warp_sums[p][w0 + 4];
#pragma unroll
        for (int off = 2; off > 0; off >>= 1)
            v += __shfl_down_sync(0xFFFFFFFFu, v, off);
        if ((lane & 3) == 0) {
            // fire-and-forget RED.MAX; v >= 0 so int cmp == float cmp
            atomicMax(&g_frame_max[t], __float_as_int(v));
        }

        // Last-block detection (1024 CTAs -> amortized 8x vs per-patch).
        unsigned int isLast = 0;
        if (lane == 0) {
            __threadfence();
            const unsigned int prev = atomicAdd(&g_count, 1u);
            isLast = (prev == (unsigned int)(GRID - 1)) ? 1u : 0u;
        }
        isLast = __shfl_sync(0xFFFFFFFFu, isLast, 0);

        if (isLast) {
            __threadfence();   // acquire: all CTAs' RED.MAXs visible
            float fm = fmaxf(__int_as_float(__ldcg(&g_frame_max[lane])), 0.0f);
#pragma unroll
            for (int off = 16; off > 0; off >>= 1)
                fm += __shfl_down_sync(0xFFFFFFFFu, fm, off);

            // Reset device state for the next graph replay.
            g_frame_max[lane] = 0;
            if (lane == 0) {
                const float scale = 0.5f / ((float)PATCH_ELEMS * (float)T);
                out[0] = logf(fm * scale);
                __threadfence();
                g_count = 0u;
            }
        }
    }
}

extern "C" void kernel_launch(void* const* d_in, const int* in_sizes, int n_in,
                              void* d_out, int out_size) {
    const float* x  = (const float*)d_in[0];
    const float* xr = (const float*)d_in[1];
    float* out = (float*)d_out;

    patch_loss_kernel<<<GRID, 256>>>(x, xr, out);
}

// round 10
// speedup vs baseline: 1.1867x; 1.1867x over previous
#include <cuda_runtime.h>
#include <math.h>

// Static geometry: x shape (1, 3, 32, 512, 512), patch 32x32
#define C       3
#define T       32
#define H       512
#define W       512
#define PS      32
#define NPATCH  (T * (H/PS) * (W/PS))   // 8192
#define PATCH_ELEMS (C * PS * PS)       // 3072
#define GRIDW   NPATCH                  // worker CTAs; +1 finalizer CTA

// Float bits of per-frame max patch-sum; sums >= 0 so int-punned atomicMax
// preserves float order and zero-init is the identity. Reset each iteration
// by the finalizer -> graph-replay safe.
__device__ int          g_frame_max[T];   // zero-initialized
__device__ unsigned int g_count;          // zero-initialized

__global__ __launch_bounds__(256, 8)
void patch_loss_kernel(const float* __restrict__ x,
                       const float* __restrict__ xr,
                       float* __restrict__ out) {
    // ---------------- Finalizer CTA (last block) ----------------
    if (blockIdx.x == GRIDW) {
        const int tid = threadIdx.x;
        if (tid < 32) {
            if (tid == 0) {
                unsigned int c;
                do {
                    __nanosleep(128);
                    asm volatile("ld.acquire.gpu.global.u32 %0, [%1];"
                                 : "=r"(c)
                                 : "l"(&g_count) : "memory");
                } while (c < (unsigned int)GRIDW);
            }
            __syncwarp();
            // Acquire above pairs with workers' release-adds: all RED.MAXs
            // are visible. Workers never load these -> no stale L1 anywhere;
            // __ldcg bypasses this CTA's L1 regardless.
            float fm = fmaxf(__int_as_float(__ldcg(&g_frame_max[tid])), 0.0f);
#pragma unroll
            for (int off = 16; off > 0; off >>= 1)
                fm += __shfl_down_sync(0xFFFFFFFFu, fm, off);

            // Reset device state for the next graph replay (ordering to the
            // next launch is provided by the kernel boundary).
            g_frame_max[tid] = 0;
            if (tid == 0) {
                g_count = 0u;
                const float scale = 0.5f / ((float)PATCH_ELEMS * (float)T);
                out[0] = logf(fm * scale);
            }
        }
        return;
    }

    // ---------------- Worker CTA: one 32x32 patch ----------------
    const int patch = blockIdx.x;          // [0, 8192)
    const int t   = patch >> 8;            // frame
    const int rem = patch & 255;
    const int ih  = rem >> 4;
    const int iw  = rem & 15;

    const int tid = threadIdx.x;           // [0, 256)
    const int r = tid >> 3;                // row within patch [0,32)
    const int q = tid & 7;                 // float4 index within row [0,8)

    const int hrow  = ih * PS + r;
    const int base0 = (t * H + hrow) * W + iw * PS + q * 4;
    const int cstride = T * H * W;

    float s = 0.0f;
#pragma unroll
    for (int c = 0; c < C; ++c) {
        const int idx = base0 + c * cstride;
        const float4 a = __ldg(reinterpret_cast<const float4*>(x  + idx));
        const float4 b = __ldg(reinterpret_cast<const float4*>(xr + idx));
        s += fabsf(a.x - b.x) + fabsf(a.y - b.y)
           + fabsf(a.z - b.z) + fabsf(a.w - b.w);
    }

    // Block reduction: warp shfl then smem across 8 warps.
#pragma unroll
    for (int off = 16; off > 0; off >>= 1)
        s += __shfl_down_sync(0xFFFFFFFFu, s, off);

    __shared__ float warp_sums[8];
    const int lane = tid & 31;
    const int wid  = tid >> 5;
    if (lane == 0) warp_sums[wid] = s;
    __syncthreads();

    if (wid == 0) {
        float v = (lane < 8) ? warp_sums[lane] : 0.0f;
#pragma unroll
        for (int off = 4; off > 0; off >>= 1)
            v += __shfl_down_sync(0xFFFFFFFFu, v, off);
        if (lane == 0) {
            // Fire-and-forget RED.MAX (v >= 0 -> int cmp == float cmp).
            atomicMax(&g_frame_max[t], __float_as_int(v));
            // Release-add: makes the RED.MAX above visible before the count
            // bump is observed. No return value -> no round-trip wait.
            asm volatile("red.release.gpu.global.add.u32 [%0], 1;"
                         :: "l"(&g_count) : "memory");
        }
    }
}

extern "C" void kernel_launch(void* const* d_in, const int* in_sizes, int n_in,
                              void* d_out, int out_size) {
    const float* x  = (const float*)d_in[0];
    const float* xr = (const float*)d_in[1];
    float* out = (float*)d_out;

    patch_loss_kernel<<<GRIDW + 1, 256>>>(x, xr, out);
}

// round 11
// speedup vs baseline: 1.1910x; 1.0037x over previous
#include <cuda_runtime.h>
#include <math.h>

// Static geometry: x shape (1, 3, 32, 512, 512), patch 32x32
#define C       3
#define T       32
#define H       512
#define W       512
#define PS      32
#define NPATCH  (T * (H/PS) * (W/PS))   // 8192
#define PATCH_ELEMS (C * PS * PS)       // 3072
#define GRIDW   NPATCH                  // worker CTAs; +1 finalizer CTA

// Float bits of per-frame max patch-sum; sums >= 0 so int-punned atomicMax
// preserves float order and zero-init is the identity. Reset by the
// finalizer each iteration -> graph-replay safe.
__device__ int          g_frame_max[T];   // zero-initialized
__device__ unsigned int g_count;          // zero-initialized

__global__ __launch_bounds__(256, 8)
void patch_loss_kernel(const float* __restrict__ x,
                       const float* __restrict__ xr,
                       float* __restrict__ out) {
    // ---------------- Finalizer CTA (last block) ----------------
    if (blockIdx.x == GRIDW) {
        const int tid = threadIdx.x;
        if (tid < 32) {
            if (tid == 0) {
                unsigned int c;
                do {
                    __nanosleep(64);
                    asm volatile("ld.acquire.gpu.global.u32 %0, [%1];"
                                 : "=r"(c)
                                 : "l"(&g_count) : "memory");
                } while (c < (unsigned int)GRIDW);
            }
            __syncwarp();
            // Acquire pairs with workers' release-adds: each CTA's RED.MAX
            // preceded its release, so all maxima are visible.
            float fm = fmaxf(__int_as_float(__ldcg(&g_frame_max[tid])), 0.0f);
#pragma unroll
            for (int off = 16; off > 0; off >>= 1)
                fm += __shfl_down_sync(0xFFFFFFFFu, fm, off);

            // Reset device state for the next graph replay.
            g_frame_max[tid] = 0;
            if (tid == 0) {
                g_count = 0u;
                const float scale = 0.5f / ((float)PATCH_ELEMS * (float)T);
                out[0] = logf(fm * scale);
            }
        }
        return;
    }

    // ---------------- Worker CTA: one 32x32 patch ----------------
    const int patch = blockIdx.x;          // [0, 8192)
    const int t   = patch >> 8;            // frame
    const int rem = patch & 255;
    const int ih  = rem >> 4;
    const int iw  = rem & 15;

    const int tid = threadIdx.x;           // [0, 256)
    const int r = tid >> 3;                // row within patch [0,32)
    const int q = tid & 7;                 // float4 index within row [0,8)

    const int hrow  = ih * PS + r;
    const int base0 = (t * H + hrow) * W + iw * PS + q * 4;
    const int cstride = T * H * W;

    // Init smem combine slot before the load latency (bar cost hidden).
    __shared__ float s_patch;
    __shared__ unsigned int s_arrived;
    if (tid == 0) { s_patch = 0.0f; s_arrived = 0u; }

    float s = 0.0f;
#pragma unroll
    for (int c = 0; c < C; ++c) {
        const int idx = base0 + c * cstride;
        // Read-once data: streaming (evict-first) loads to lighten L2.
        const float4 a = __ldcs(reinterpret_cast<const float4*>(x  + idx));
        const float4 b = __ldcs(reinterpret_cast<const float4*>(xr + idx));
        s += fabsf(a.x - b.x) + fabsf(a.y - b.y)
           + fabsf(a.z - b.z) + fabsf(a.w - b.w);
    }
    __syncthreads();   // s_patch/s_arrived init visible (overlapped with loads)

    // Warp shfl reduce, then smem-atomic combine: last-arriving warp leader
    // fires the global atomics. No second __syncthreads, no 2-phase tree.
#pragma unroll
    for (int off = 16; off > 0; off >>= 1)
        s += __shfl_down_sync(0xFFFFFFFFu, s, off);

    if ((tid & 31) == 0) {
        atomicAdd(&s_patch, s);                 // ATOMS
        __threadfence_block();
        const unsigned int rank = atomicAdd(&s_arrived, 1u);
        if (rank == 7u) {                       // last warp of this CTA
            const float v = s_patch;            // all 8 adds complete
            // fire-and-forget RED.MAX (v >= 0 -> int cmp == float cmp)
            atomicMax(&g_frame_max[t], __float_as_int(v));
            // release makes the RED.MAX visible before the count bump
            asm volatile("red.release.gpu.global.add.u32 [%0], 1;"
                         :: "l"(&g_count) : "memory");
        }
    }
}

extern "C" void kernel_launch(void* const* d_in, const int* in_sizes, int n_in,
                              void* d_out, int out_size) {
    const float* x  = (const float*)d_in[0];
    const float* xr = (const float*)d_in[1];
    float* out = (float*)d_out;

    patch_loss_kernel<<<GRIDW + 1, 256>>>(x, xr, out);
}